// round 7
// baseline (speedup 1.0000x reference)
#include <cuda_runtime.h>

typedef unsigned long long ull;

#define BS 2
#define NN 2048
#define DIN 128
#define DOUT 128
#define H 8
#define DK 16

#define TMA 256
#define NT (NN / TMA)       // 8 tiles
#define STRD (TMA + 4)      // transposed [d][m] rows, conflict-free LDS.128

// -------- scratch (no allocs allowed) --------
__device__ float g_Q[(size_t)BS*H*NN*DK];
__device__ float g_K[(size_t)BS*H*NN*DK];
__device__ float g_V[(size_t)BS*H*NN*DK];

// ---------- f32x2 helpers ----------
__device__ __forceinline__ void ffma2(ull& d, ull a, ull b) {
    asm("fma.rn.f32x2 %0, %1, %2, %0;" : "+l"(d) : "l"(a), "l"(b));
}
__device__ __forceinline__ ull pk2(float a, float b) {
    ull r; asm("mov.b64 %0, {%1, %2};" : "=l"(r) : "f"(a), "f"(b)); return r;
}
__device__ __forceinline__ float2 upk(ull v) {
    float2 r; asm("mov.b64 {%0, %1}, %2;" : "=f"(r.x), "=f"(r.y) : "l"(v)); return r;
}

// ============================================================
// Projection: y = X @ W^T + b, written as [b][h][n][dk]
// ============================================================
#define PBM 64
__global__ __launch_bounds__(256, 2) void proj_kernel(
    const float* __restrict__ X,
    const float* __restrict__ Wq, const float* __restrict__ bq,
    const float* __restrict__ Wk, const float* __restrict__ bk,
    const float* __restrict__ Wv, const float* __restrict__ bv)
{
    __shared__ float Xs[PBM][33];
    __shared__ float Wt[32][128];

    int tid = threadIdx.x;
    int sel = blockIdx.y;
    const float* W    = (sel == 0) ? Wq : ((sel == 1) ? Wk : Wv);
    const float* bias = (sel == 0) ? bq : ((sel == 1) ? bk : bv);
    float* dst        = (sel == 0) ? g_Q : ((sel == 1) ? g_K : g_V);

    int tx = tid & 63;
    int ty = tid >> 6;
    int row0 = blockIdx.x * PBM;

    float acc0[16], acc1[16];
#pragma unroll
    for (int i = 0; i < 16; i++) { acc0[i] = 0.f; acc1[i] = 0.f; }

    for (int k0 = 0; k0 < DIN; k0 += 32) {
        __syncthreads();
#pragma unroll
        for (int r = 0; r < 2; r++) {
            int i = tid + 256 * r;
            int xr = i >> 3;
            int xc = (i & 7) << 2;
            float4 xv = *(const float4*)(X + (size_t)(row0 + xr) * DIN + k0 + xc);
            Xs[xr][xc + 0] = xv.x; Xs[xr][xc + 1] = xv.y;
            Xs[xr][xc + 2] = xv.z; Xs[xr][xc + 3] = xv.w;
        }
#pragma unroll
        for (int r = 0; r < 4; r++) {
            int i = tid + 256 * r;
            int o  = i >> 3;
            int kc = (i & 7) << 2;
            float4 wv = *(const float4*)(W + (size_t)o * DIN + k0 + kc);
            Wt[kc + 0][o] = wv.x; Wt[kc + 1][o] = wv.y;
            Wt[kc + 2][o] = wv.z; Wt[kc + 3][o] = wv.w;
        }
        __syncthreads();
#pragma unroll
        for (int kk = 0; kk < 32; kk++) {
            float w0 = Wt[kk][tx];
            float w1 = Wt[kk][tx + 64];
#pragma unroll
            for (int rr = 0; rr < 16; rr++) {
                float xv = Xs[ty * 16 + rr][kk];
                acc0[rr] = fmaf(xv, w0, acc0[rr]);
                acc1[rr] = fmaf(xv, w1, acc1[rr]);
            }
        }
    }

    float b0 = bias[tx], b1 = bias[tx + 64];
    int c0 = tx, c1 = tx + 64;
#pragma unroll
    for (int rr = 0; rr < 16; rr++) {
        int grow = row0 + ty * 16 + rr;
        int b = grow / NN, n = grow % NN;
        dst[(((size_t)b * H + (c0 >> 4)) * NN + n) * DK + (c0 & 15)] = acc0[rr] + b0;
        dst[(((size_t)b * H + (c1 >> 4)) * NN + n) * DK + (c1 & 15)] = acc1[rr] + b1;
    }
}

// ============================================================
// Fused attention, 4 rows/warp, score-store:
// Pass 1: QK (f32x2 row-pair packed, dup-k) + bias + mask -> RAW
//         scores to scorep, online (max,sum) in regs.
// Pass 2: LDG raw scores, p = exp(s-mx)*inv, overwrite p,
//         PV f32x2 row-pair packed (dup-v).
// q-packs live only in pass 1, PV accs only in pass 2 (reg overlay).
// One smem tile buffer. grid (64,8,2), block 256.
// ============================================================
#define ROWS_PB 32

__global__ __launch_bounds__(256, 2) void attn_kernel(
    const float* __restrict__ sp, const int* __restrict__ adj,
    float* __restrict__ outp, float* __restrict__ scorep)
{
    __shared__ float ts[DK][STRD];   // transposed: [d][m]

    int tid = threadIdx.x;
    int w = tid >> 5;
    int l = tid & 31;
    int h = blockIdx.y, b = blockIdx.z;
    int bh = b * H + h;
    int n0 = blockIdx.x * ROWS_PB + w * 4;    // rows n0..n0+3

    const float* kb = g_K + (size_t)bh * NN * DK;
    const float* vb = g_V + (size_t)bh * NN * DK;

    size_t arow[4];
#pragma unroll
    for (int r = 0; r < 4; r++) arow[r] = ((size_t)bh * NN + n0 + r) * NN;

    float mx[4], S[4];
#pragma unroll
    for (int r = 0; r < 4; r++) { mx[r] = -3.0e38f; S[r] = 0.f; }

    // ================= Pass 1: scores + stats =================
    {
        // q packs (row-pair): qq[p][d] = (q_{2p}[d], q_{2p+1}[d]) * 0.25
        ull qq[2][DK];
#pragma unroll
        for (int p = 0; p < 2; p++) {
            const float* qa = g_Q + ((size_t)bh * NN + n0 + 2 * p    ) * DK;
            const float* qb = g_Q + ((size_t)bh * NN + n0 + 2 * p + 1) * DK;
#pragma unroll
            for (int d4 = 0; d4 < 4; d4++) {
                float4 ta = *(const float4*)(qa + 4 * d4);
                float4 tb = *(const float4*)(qb + 4 * d4);
                qq[p][4*d4+0] = pk2(ta.x * 0.25f, tb.x * 0.25f);
                qq[p][4*d4+1] = pk2(ta.y * 0.25f, tb.y * 0.25f);
                qq[p][4*d4+2] = pk2(ta.z * 0.25f, tb.z * 0.25f);
                qq[p][4*d4+3] = pk2(ta.w * 0.25f, tb.w * 0.25f);
            }
        }

        for (int t = 0; t < NT; t++) {
            __syncthreads();
#pragma unroll
            for (int r = 0; r < 4; r++) {
                int f = tid + 256 * r;            // float4 idx 0..1023
                int m = f >> 2;
                int dg = (f & 3) << 2;
                float4 kv = *(const float4*)(kb + ((size_t)(t * TMA + m)) * DK + dg);
                ts[dg + 0][m] = kv.x; ts[dg + 1][m] = kv.y;
                ts[dg + 2][m] = kv.z; ts[dg + 3][m] = kv.w;
            }
            __syncthreads();

#pragma unroll
            for (int c = 0; c < 2; c++) {
                int mm = c * 128 + 4 * l;
                int mg = t * TMA + mm;

                ull acc[2][4];
#pragma unroll
                for (int p = 0; p < 2; p++)
#pragma unroll
                    for (int m = 0; m < 4; m++) acc[p][m] = 0ull;

#pragma unroll
                for (int d = 0; d < DK; d++) {
                    float4 kv = *(const float4*)&ts[d][mm];
                    ull k0 = pk2(kv.x, kv.x), k1 = pk2(kv.y, kv.y);
                    ull k2 = pk2(kv.z, kv.z), k3 = pk2(kv.w, kv.w);
                    ffma2(acc[0][0], qq[0][d], k0); ffma2(acc[0][1], qq[0][d], k1);
                    ffma2(acc[0][2], qq[0][d], k2); ffma2(acc[0][3], qq[0][d], k3);
                    ffma2(acc[1][0], qq[1][d], k0); ffma2(acc[1][1], qq[1][d], k1);
                    ffma2(acc[1][2], qq[1][d], k2); ffma2(acc[1][3], qq[1][d], k3);
                }

                float sc[4][4];
#pragma unroll
                for (int p = 0; p < 2; p++)
#pragma unroll
                    for (int m = 0; m < 4; m++) {
                        float2 f2 = upk(acc[p][m]);
                        sc[2 * p + 0][m] = f2.x;
                        sc[2 * p + 1][m] = f2.y;
                    }

#pragma unroll
                for (int r = 0; r < 4; r++) {
                    int nr = n0 + r;
                    float4 sv = *(const float4*)(sp + (size_t)nr * NN + mg);
                    int4 av = *(const int4*)(adj + ((size_t)b * NN + nr) * NN + mg);
                    sv.x = (mg + 0 == nr) ? 0.f : sv.x;
                    sv.y = (mg + 1 == nr) ? 0.f : sv.y;
                    sv.z = (mg + 2 == nr) ? 0.f : sv.z;
                    sv.w = (mg + 3 == nr) ? 0.f : sv.w;
                    float t0 = av.x ? (sc[r][0] + sv.x) : -1e10f;
                    float t1 = av.y ? (sc[r][1] + sv.y) : -1e10f;
                    float t2 = av.z ? (sc[r][2] + sv.z) : -1e10f;
                    float t3 = av.w ? (sc[r][3] + sv.w) : -1e10f;

                    *(float4*)(scorep + arow[r] + mg) = make_float4(t0, t1, t2, t3);

                    float cm = fmaxf(fmaxf(t0, t1), fmaxf(t2, t3));
                    float nm = fmaxf(mx[r], cm);
                    S[r] = S[r] * __expf(mx[r] - nm)
                         + __expf(t0 - nm) + __expf(t1 - nm)
                         + __expf(t2 - nm) + __expf(t3 - nm);
                    mx[r] = nm;
                }
            }
        }
    }

    // warp-combine (max,sum) exactly
    float inv[4];
#pragma unroll
    for (int r = 0; r < 4; r++) {
        float m_r = mx[r], s_r = S[r];
#pragma unroll
        for (int off = 16; off; off >>= 1) {
            float mo = __shfl_xor_sync(0xffffffffu, m_r, off);
            float so = __shfl_xor_sync(0xffffffffu, s_r, off);
            float nm = fmaxf(m_r, mo);
            s_r = s_r * __expf(m_r - nm) + so * __expf(mo - nm);
            m_r = nm;
        }
        mx[r] = m_r;
        inv[r] = 1.f / s_r;
    }

    // ================= Pass 2: normalize + PV (row-pair packed) =========
    ull op[2][DK];   // op[p][d] = (o_{2p}[d], o_{2p+1}[d])
#pragma unroll
    for (int p = 0; p < 2; p++)
#pragma unroll
        for (int d = 0; d < DK; d++) op[p][d] = 0ull;

    for (int t = 0; t < NT; t++) {
        __syncthreads();
#pragma unroll
        for (int r = 0; r < 4; r++) {
            int f = tid + 256 * r;
            int m = f >> 2;
            int dg = (f & 3) << 2;
            float4 vv = *(const float4*)(vb + ((size_t)(t * TMA + m)) * DK + dg);
            ts[dg + 0][m] = vv.x; ts[dg + 1][m] = vv.y;
            ts[dg + 2][m] = vv.z; ts[dg + 3][m] = vv.w;
        }
        __syncthreads();

#pragma unroll
        for (int c = 0; c < 2; c++) {
            int mm = c * 128 + 4 * l;
            int mg = t * TMA + mm;

            float pr[4][4];
#pragma unroll
            for (int r = 0; r < 4; r++) {
                float4 rs = *(const float4*)(scorep + arow[r] + mg);
                float p0 = __expf(rs.x - mx[r]) * inv[r];
                float p1 = __expf(rs.y - mx[r]) * inv[r];
                float p2 = __expf(rs.z - mx[r]) * inv[r];
                float p3 = __expf(rs.w - mx[r]) * inv[r];
                *(float4*)(scorep + arow[r] + mg) = make_float4(p0, p1, p2, p3);
                pr[r][0] = p0; pr[r][1] = p1; pr[r][2] = p2; pr[r][3] = p3;
            }

            ull pp[2][4];
#pragma unroll
            for (int m = 0; m < 4; m++) {
                pp[0][m] = pk2(pr[0][m], pr[1][m]);
                pp[1][m] = pk2(pr[2][m], pr[3][m]);
            }

#pragma unroll
            for (int d = 0; d < DK; d++) {
                float4 vv = *(const float4*)&ts[d][mm];
                ull v0 = pk2(vv.x, vv.x), v1 = pk2(vv.y, vv.y);
                ull v2 = pk2(vv.z, vv.z), v3 = pk2(vv.w, vv.w);
                ffma2(op[0][d], pp[0][0], v0); ffma2(op[0][d], pp[0][1], v1);
                ffma2(op[0][d], pp[0][2], v2); ffma2(op[0][d], pp[0][3], v3);
                ffma2(op[1][d], pp[1][0], v0); ffma2(op[1][d], pp[1][1], v1);
                ffma2(op[1][d], pp[1][2], v2); ffma2(op[1][d], pp[1][3], v3);
            }
        }
    }

    // unpack row-pairs, butterfly reduce across lanes
    float o[4][DK];
#pragma unroll
    for (int d = 0; d < DK; d++) {
        float2 e0 = upk(op[0][d]); o[0][d] = e0.x; o[1][d] = e0.y;
        float2 e1 = upk(op[1][d]); o[2][d] = e1.x; o[3][d] = e1.y;
    }
#pragma unroll
    for (int off = 16; off; off >>= 1) {
#pragma unroll
        for (int r = 0; r < 4; r++)
#pragma unroll
            for (int d = 0; d < DK; d++)
                o[r][d] += __shfl_xor_sync(0xffffffffu, o[r][d], off);
    }

    // out layout: out[(b*N+n)*128 + d*8 + h]; lane r writes row n0+r
    if (outp && l < 4) {
        int n = n0 + l;
        float* ob = outp + ((size_t)b * NN + n) * DOUT + h;
#pragma unroll
        for (int d = 0; d < DK; d++) ob[(size_t)d * H] = o[l][d];
    }
}

// ============================================================
extern "C" void kernel_launch(void* const* d_in, const int* in_sizes, int n_in,
                              void* d_out, int out_size) {
    const float* x   = (const float*)d_in[0];
    const int*   adj = (const int*)  d_in[1];
    const float* sp  = (const float*)d_in[2];
    const float* Wq  = (const float*)d_in[3];
    const float* bq  = (const float*)d_in[4];
    const float* Wk  = (const float*)d_in[5];
    const float* bk  = (const float*)d_in[6];
    const float* Wv  = (const float*)d_in[7];
    const float* bv  = (const float*)d_in[8];

    const long long OUT_ELEMS  = (long long)BS * NN * DOUT;              // 524288
    const long long ATTN_ELEMS = (long long)BS * H * NN * (long long)NN; // 67108864

    float* base  = (float*)d_out;
    float* outp  = nullptr;
    float* attnp = nullptr;
    long long osz = (long long)out_size;
    if (osz >= OUT_ELEMS + ATTN_ELEMS) { outp = base; attnp = base + OUT_ELEMS; }
    else if (osz == ATTN_ELEMS)        { attnp = base; }
    else                               { outp = base; }

    float* scorep = attnp ? attnp : base;

    dim3 pgrid(BS * NN / PBM, 3);
    proj_kernel<<<pgrid, 256>>>(x, Wq, bq, Wk, bk, Wv, bv);

    dim3 agrid(NN / ROWS_PB, H, BS);
    attn_kernel<<<agrid, 256>>>(sp, adj, outp, scorep);
}